// round 12
// baseline (speedup 1.0000x reference)
#include <cuda_runtime.h>
#include <math.h>

// ---------------------------------------------------------------------------
// NeuralODE Tsit5, TWO trajectories per warp, f32x2-packed, FSAL,
// LDS ping-pong broadcasts. W1 lives in SMEM (transposed, conflict-free),
// shared by both trajectories -> no register spills.
// Lane L owns components (2L, 2L+1) of both trajectories.
// ---------------------------------------------------------------------------

#define DIM      64
#define HID      32
#define TRAJ_LEN 11
#define MAXI     64

typedef unsigned long long u64;

__device__ __forceinline__ u64 pk2(float lo, float hi) {
    u64 r; asm("mov.b64 %0,{%1,%2};" : "=l"(r) : "f"(lo), "f"(hi)); return r;
}
__device__ __forceinline__ u64 pkb(float x) { return pk2(x, x); }
__device__ __forceinline__ void upk(u64 v, float& a, float& b) {
    asm("mov.b64 {%0,%1},%2;" : "=f"(a), "=f"(b) : "l"(v));
}
__device__ __forceinline__ u64 fma2(u64 a, u64 b, u64 c) {
    u64 d; asm("fma.rn.f32x2 %0,%1,%2,%3;" : "=l"(d) : "l"(a), "l"(b), "l"(c)); return d;
}
__device__ __forceinline__ u64 add2(u64 a, u64 b) {
    u64 d; asm("add.rn.f32x2 %0,%1,%2;" : "=l"(d) : "l"(a), "l"(b)); return d;
}
__device__ __forceinline__ u64 mul2(u64 a, u64 b) {
    u64 d; asm("mul.rn.f32x2 %0,%1,%2;" : "=l"(d) : "l"(a), "l"(b)); return d;
}
__device__ __forceinline__ float hsum2(u64 v) { float a, b; upk(v, a, b); return a + b; }

// Tsit5 tableau (f32) — C_ namespace, no identifier collisions
#define C_A21 ((float)0.161)
#define C_A31 ((float)-0.008480655492356989)
#define C_A32 ((float)0.335480655492357)
#define C_A41 ((float)2.8971530571054935)
#define C_A42 ((float)-6.359448489975075)
#define C_A43 ((float)4.3622954328695815)
#define C_A51 ((float)5.325864828439257)
#define C_A52 ((float)-11.748883564062828)
#define C_A53 ((float)7.4955393428898365)
#define C_A54 ((float)-0.09249506636175525)
#define C_A61 ((float)5.86145544294642)
#define C_A62 ((float)-12.92096931784711)
#define C_A63 ((float)8.159367898576159)
#define C_A64 ((float)-0.071584973281401)
#define C_A65 ((float)-0.028269050394068383)
#define C_B1  ((float)0.09646076681806523)
#define C_B2  ((float)0.01)
#define C_B3  ((float)0.4798896504144996)
#define C_B4  ((float)1.379008574103742)
#define C_B5  ((float)-3.290069515436081)
#define C_B6  ((float)2.324710524099774)
#define C_E1  ((float)-0.00178001105222577714)
#define C_E2  ((float)-0.0008164344596567469)
#define C_E3  ((float)0.007880878010261995)
#define C_E4  ((float)-0.1447110071732629)
#define C_E5  ((float)0.5823571654525552)
#define C_E6  ((float)-0.45808210592918697)
#define C_E7  ((float)0.015151515151515152)

#define RTOL 1e-3f
#define ATOL 1e-6f

__device__ __forceinline__ float softplus_f(float x) {
    return fmaxf(x, 0.0f) + __logf(1.0f + __expf(-fabsf(x)));
}

// Dual ping-pong broadcast: both trajectories share ONE syncwarp.
#define BC64x2(ZA, ZB) do { bsel ^= 1;                                          \
    float* _ba = bsel ? bA0 : bA1; float* _bb = bsel ? bB0 : bB1;               \
    ((u64*)_ba)[lane] = (ZA); ((u64*)_bb)[lane] = (ZB);                         \
    __syncwarp(); curA = _ba; curB = _bb; } while (0)
#define BC32x2(HA, HB) do { bsel ^= 1;                                          \
    float* _ba = bsel ? bA0 : bA1; float* _bb = bsel ? bB0 : bB1;               \
    _ba[lane] = (HA); _bb[lane] = (HB);                                         \
    __syncwarp(); curA = _ba; curB = _bb; } while (0)

// Dual MLP eval. mv1 weights stream from SMEM (transposed, conflict-free),
// one weight load feeds both trajectories. mv2/mv3 weights in registers.
#define FEVAL2(ZA, ZB, KA, KB) do {                                             \
    BC64x2(ZA, ZB);                                                             \
    { const ulonglong2* _zA = (const ulonglong2*)curA;                          \
      const ulonglong2* _zB = (const ulonglong2*)curB;                          \
      u64 _aA0=0,_aA1=0,_aA2=0,_aA3=0, _aB0=0,_aB1=0,_aB2=0,_aB3=0;             \
      _Pragma("unroll")                                                         \
      for (int _j = 0; _j < 8; _j++) {                                          \
          ulonglong2 _w0 = w1sv[(2*_j+0)*32 + lane];                            \
          ulonglong2 _w1 = w1sv[(2*_j+1)*32 + lane];                            \
          ulonglong2 _qA = _zA[2*_j], _rA = _zA[2*_j+1];                        \
          ulonglong2 _qB = _zB[2*_j], _rB = _zB[2*_j+1];                        \
          _aA0 = fma2(_w0.x, _qA.x, _aA0);                                      \
          _aB0 = fma2(_w0.x, _qB.x, _aB0);                                      \
          _aA1 = fma2(_w0.y, _qA.y, _aA1);                                      \
          _aB1 = fma2(_w0.y, _qB.y, _aB1);                                      \
          _aA2 = fma2(_w1.x, _rA.x, _aA2);                                      \
          _aB2 = fma2(_w1.x, _rB.x, _aB2);                                      \
          _aA3 = fma2(_w1.y, _rA.y, _aA3);                                      \
          _aB3 = fma2(_w1.y, _rB.y, _aB3);                                      \
      }                                                                         \
      float _h1A = softplus_f(hsum2(add2(add2(_aA0,_aA1), add2(_aA2,_aA3))) + bb1); \
      float _h1B = softplus_f(hsum2(add2(add2(_aB0,_aB1), add2(_aB2,_aB3))) + bb1); \
      BC32x2(_h1A, _h1B);                                                       \
      const ulonglong2* _hA = (const ulonglong2*)curA;                          \
      const ulonglong2* _hB = (const ulonglong2*)curB;                          \
      u64 _sA0=0,_sA1=0, _sB0=0,_sB1=0;                                         \
      _Pragma("unroll")                                                         \
      for (int _j = 0; _j < 4; _j++) {                                          \
          ulonglong2 _qA = _hA[2*_j], _gA = _hA[2*_j+1];                        \
          ulonglong2 _qB = _hB[2*_j], _gB = _hB[2*_j+1];                        \
          _sA0 = fma2(w2p[4*_j+0], _qA.x, _sA0);                                \
          _sB0 = fma2(w2p[4*_j+0], _qB.x, _sB0);                                \
          _sA1 = fma2(w2p[4*_j+1], _qA.y, _sA1);                                \
          _sB1 = fma2(w2p[4*_j+1], _qB.y, _sB1);                                \
          _sA0 = fma2(w2p[4*_j+2], _gA.x, _sA0);                                \
          _sB0 = fma2(w2p[4*_j+2], _gB.x, _sB0);                                \
          _sA1 = fma2(w2p[4*_j+3], _gA.y, _sA1);                                \
          _sB1 = fma2(w2p[4*_j+3], _gB.y, _sB1);                                \
      }                                                                         \
      float _h2A = softplus_f(hsum2(add2(_sA0,_sA1)) + bb2);                    \
      float _h2B = softplus_f(hsum2(add2(_sB0,_sB1)) + bb2);                    \
      BC32x2(_h2A, _h2B);                                                       \
      const ulonglong2* _gpA = (const ulonglong2*)curA;                         \
      const ulonglong2* _gpB = (const ulonglong2*)curB;                         \
      u64 _cA0=0,_cA1=0,_dA0=0,_dA1=0, _cB0=0,_cB1=0,_dB0=0,_dB1=0;             \
      _Pragma("unroll")                                                         \
      for (int _j = 0; _j < 4; _j++) {                                          \
          ulonglong2 _qA = _gpA[2*_j], _gA = _gpA[2*_j+1];                      \
          ulonglong2 _qB = _gpB[2*_j], _gB = _gpB[2*_j+1];                      \
          _cA0 = fma2(w3p0[4*_j+0], _qA.x, _cA0);                               \
          _cB0 = fma2(w3p0[4*_j+0], _qB.x, _cB0);                               \
          _cA1 = fma2(w3p0[4*_j+1], _qA.y, _cA1);                               \
          _cB1 = fma2(w3p0[4*_j+1], _qB.y, _cB1);                               \
          _cA0 = fma2(w3p0[4*_j+2], _gA.x, _cA0);                               \
          _cB0 = fma2(w3p0[4*_j+2], _gB.x, _cB0);                               \
          _cA1 = fma2(w3p0[4*_j+3], _gA.y, _cA1);                               \
          _cB1 = fma2(w3p0[4*_j+3], _gB.y, _cB1);                               \
          _dA0 = fma2(w3p1[4*_j+0], _qA.x, _dA0);                               \
          _dB0 = fma2(w3p1[4*_j+0], _qB.x, _dB0);                               \
          _dA1 = fma2(w3p1[4*_j+1], _qA.y, _dA1);                               \
          _dB1 = fma2(w3p1[4*_j+1], _qB.y, _dB1);                               \
          _dA0 = fma2(w3p1[4*_j+2], _gA.x, _dA0);                               \
          _dB0 = fma2(w3p1[4*_j+2], _gB.x, _dB0);                               \
          _dA1 = fma2(w3p1[4*_j+3], _gA.y, _dA1);                               \
          _dB1 = fma2(w3p1[4*_j+3], _gB.y, _dB1);                               \
      }                                                                         \
      (KA) = pk2(hsum2(add2(_cA0,_cA1)) + b3x, hsum2(add2(_dA0,_dA1)) + b3y);   \
      (KB) = pk2(hsum2(add2(_cB0,_cB1)) + b3x, hsum2(add2(_dB0,_dB1)) + b3y);   \
    } } while (0)

__global__ void __launch_bounds__(32, 8)
ode_kernel(const float* __restrict__ x0s,
           const float* __restrict__ gW1, const float* __restrict__ gb1,
           const float* __restrict__ gW2, const float* __restrict__ gb2,
           const float* __restrict__ gW3, const float* __restrict__ gb3,
           const int*   __restrict__ Tp,
           float* __restrict__ out, int nTraj, int writeN)
{
    // W1 transposed in smem: w1sv[j*32 + L] = (W1[L][4j..4j+1], W1[L][4j+2..4j+3])
    // as two packed f32x2. Consecutive lanes -> consecutive 16B: conflict-free.
    __shared__ __align__(16) ulonglong2 w1sv[32 * 32 / 2];   // 8 KB
    __shared__ __align__(16) float bA0[DIM], bA1[DIM], bB0[DIM], bB1[DIM];

    const int lane  = threadIdx.x & 31;
    const int trajA = blockIdx.x * 2;
    const int trajB = trajA + 1;
    if (trajA >= nTraj) return;
    const bool hasB = (trajB < nTraj);

    int bsel = 0;
    const float* curA = bA0;
    const float* curB = bB0;

    // Fill W1 smem (transposed). Lane L owns row L of W1.
    {
        const u64* r1 = (const u64*)(gW1 + lane * DIM);
        #pragma unroll
        for (int j = 0; j < 16; j++) {
            ulonglong2 w;
            w.x = __ldg(r1 + 2*j);
            w.y = __ldg(r1 + 2*j + 1);
            w1sv[j * 32 + lane] = w;
        }
    }

    // W2/W3 weights in registers: lane owns W2 row L, W3 rows 2L, 2L+1.
    u64 w2p[16], w3p0[16], w3p1[16];
    {
        const u64* r2 = (const u64*)(gW2 + lane * HID);
        #pragma unroll
        for (int j = 0; j < 16; j++) w2p[j] = __ldg(r2 + j);
        const u64* r3a = (const u64*)(gW3 + (2*lane)   * HID);
        const u64* r3b = (const u64*)(gW3 + (2*lane+1) * HID);
        #pragma unroll
        for (int j = 0; j < 16; j++) { w3p0[j] = __ldg(r3a + j); w3p1[j] = __ldg(r3b + j); }
    }
    const float bb1 = __ldg(gb1 + lane);
    const float bb2 = __ldg(gb2 + lane);
    const float b3x = __ldg(gb3 + 2*lane);
    const float b3y = __ldg(gb3 + 2*lane + 1);
    __syncwarp();

    u64 yA = ((const u64*)(x0s + (size_t)trajA * DIM))[lane];
    u64 yB = hasB ? ((const u64*)(x0s + (size_t)trajB * DIM))[lane] : yA;

    float* orowA = out + (size_t)trajA * (TRAJ_LEN * DIM);
    float* orowB = out + (size_t)trajB * (TRAJ_LEN * DIM);
    ((u64*)orowA)[lane] = yA;
    if (hasB) ((u64*)orowB)[lane] = yB;

    const float Tf   = (float)__ldg(Tp);
    const float step = Tf / 10.0f;
    float tA = 0.0f, tB = 0.0f;
    float dtA = 1e-3f, dtB = 1e-3f;
    int   nA = 0, nB = 0;

    // FSAL seed
    u64 k1A, k1B;
    FEVAL2(yA, yB, k1A, k1B);

    for (int iv = 1; iv < TRAJ_LEN; iv++) {
        const float t_target = step * (float)iv;

        for (int it = 0; it < MAXI; it++) {
            float remA = t_target - tA;
            float remB = t_target - tB;
            bool doneA = (remA <= 1e-12f);
            bool doneB = (remB <= 1e-12f);
            if (doneA && doneB) break;          // ref freezes state when done: exact
            nA += doneA ? 0 : 1;
            nB += doneB ? 0 : 1;

            float hA = fminf(dtA, fmaxf(remA, 0.0f));
            float hB = fminf(dtB, fmaxf(remB, 0.0f));

            u64 k2A,k3A,k4A,k5A,k6A,k7A, k2B,k3B,k4B,k5B,k6B,k7B, zA, zB;

            zA = fma2(pkb(hA*C_A21), k1A, yA);
            zB = fma2(pkb(hB*C_A21), k1B, yB);
            FEVAL2(zA, zB, k2A, k2B);

            zA = fma2(pkb(hA*C_A31), k1A, fma2(pkb(hA*C_A32), k2A, yA));
            zB = fma2(pkb(hB*C_A31), k1B, fma2(pkb(hB*C_A32), k2B, yB));
            FEVAL2(zA, zB, k3A, k3B);

            zA = fma2(pkb(hA*C_A41), k1A, fma2(pkb(hA*C_A42), k2A, fma2(pkb(hA*C_A43), k3A, yA)));
            zB = fma2(pkb(hB*C_A41), k1B, fma2(pkb(hB*C_A42), k2B, fma2(pkb(hB*C_A43), k3B, yB)));
            FEVAL2(zA, zB, k4A, k4B);

            zA = fma2(pkb(hA*C_A51), k1A, fma2(pkb(hA*C_A52), k2A, fma2(pkb(hA*C_A53), k3A,
                 fma2(pkb(hA*C_A54), k4A, yA))));
            zB = fma2(pkb(hB*C_A51), k1B, fma2(pkb(hB*C_A52), k2B, fma2(pkb(hB*C_A53), k3B,
                 fma2(pkb(hB*C_A54), k4B, yB))));
            FEVAL2(zA, zB, k5A, k5B);

            zA = fma2(pkb(hA*C_A61), k1A, fma2(pkb(hA*C_A62), k2A, fma2(pkb(hA*C_A63), k3A,
                 fma2(pkb(hA*C_A64), k4A, fma2(pkb(hA*C_A65), k5A, yA)))));
            zB = fma2(pkb(hB*C_A61), k1B, fma2(pkb(hB*C_A62), k2B, fma2(pkb(hB*C_A63), k3B,
                 fma2(pkb(hB*C_A64), k4B, fma2(pkb(hB*C_A65), k5B, yB)))));
            FEVAL2(zA, zB, k6A, k6B);

            u64 y5A = fma2(pkb(hA*C_B1), k1A, fma2(pkb(hA*C_B2), k2A, fma2(pkb(hA*C_B3), k3A,
                      fma2(pkb(hA*C_B4), k4A, fma2(pkb(hA*C_B5), k5A, fma2(pkb(hA*C_B6), k6A, yA))))));
            u64 y5B = fma2(pkb(hB*C_B1), k1B, fma2(pkb(hB*C_B2), k2B, fma2(pkb(hB*C_B3), k3B,
                      fma2(pkb(hB*C_B4), k4B, fma2(pkb(hB*C_B5), k5B, fma2(pkb(hB*C_B6), k6B, yB))))));

            FEVAL2(y5A, y5B, k7A, k7B);

            u64 errA = fma2(pkb(hA*C_E1), k1A, fma2(pkb(hA*C_E2), k2A, fma2(pkb(hA*C_E3), k3A,
                       fma2(pkb(hA*C_E4), k4A, fma2(pkb(hA*C_E5), k5A, fma2(pkb(hA*C_E6), k6A,
                       mul2(pkb(hA*C_E7), k7A)))))));
            u64 errB = fma2(pkb(hB*C_E1), k1B, fma2(pkb(hB*C_E2), k2B, fma2(pkb(hB*C_E3), k3B,
                       fma2(pkb(hB*C_E4), k4B, fma2(pkb(hB*C_E5), k5B, fma2(pkb(hB*C_E6), k6B,
                       mul2(pkb(hB*C_E7), k7B)))))));

            float ylo, yhi, y5lo, y5hi, elo, ehi;
            upk(yA, ylo, yhi); upk(y5A, y5lo, y5hi); upk(errA, elo, ehi);
            float sclo = fmaf(RTOL, fmaxf(fabsf(ylo), fabsf(y5lo)), ATOL);
            float schi = fmaf(RTOL, fmaxf(fabsf(yhi), fabsf(y5hi)), ATOL);
            float rlo = __fdividef(elo, sclo);
            float rhi = __fdividef(ehi, schi);
            float ssA = fmaf(rlo, rlo, rhi * rhi);

            upk(yB, ylo, yhi); upk(y5B, y5lo, y5hi); upk(errB, elo, ehi);
            sclo = fmaf(RTOL, fmaxf(fabsf(ylo), fabsf(y5lo)), ATOL);
            schi = fmaf(RTOL, fmaxf(fabsf(yhi), fabsf(y5hi)), ATOL);
            rlo = __fdividef(elo, sclo);
            rhi = __fdividef(ehi, schi);
            float ssB = fmaf(rlo, rlo, rhi * rhi);

            #pragma unroll
            for (int o = 16; o; o >>= 1) {
                ssA += __shfl_xor_sync(0xffffffffu, ssA, o);
                ssB += __shfl_xor_sync(0xffffffffu, ssB, o);
            }

            bool acceptA = (ssA <= 64.0f);      // == (max(sqrt(ss/64),1e-10) <= 1)
            bool acceptB = (ssB <= 64.0f);
            float qA = fmaxf(ssA * 0.015625f, 1e-20f);
            float qB = fmaxf(ssB * 0.015625f, 1e-20f);
            float facA = fminf(fmaxf(0.9f * __powf(qA, -0.1f), 0.1f), 5.0f);
            float facB = fminf(fmaxf(0.9f * __powf(qB, -0.1f), 0.1f), 5.0f);

            if (!doneA) {
                if (acceptA) { tA += hA; yA = y5A; k1A = k7A; }
                dtA = fmaxf(hA * facA, 1e-8f);
            }
            if (!doneB) {
                if (acceptB) { tB += hB; yB = y5B; k1B = k7B; }
                dtB = fmaxf(hB * facB, 1e-8f);
            }
        }

        ((u64*)(orowA + iv * DIM))[lane] = yA;
        if (hasB) ((u64*)(orowB + iv * DIM))[lane] = yB;
    }

    if (writeN && lane == 0)
        atomicAdd(out + (size_t)nTraj * TRAJ_LEN * DIM, (float)(nA + (hasB ? nB : 0)));
}

extern "C" void kernel_launch(void* const* d_in, const int* in_sizes, int n_in,
                              void* d_out, int out_size)
{
    const float* x0s = (const float*)d_in[0];
    const float* W1  = (const float*)d_in[1];
    const float* b1  = (const float*)d_in[2];
    const float* W2  = (const float*)d_in[3];
    const float* b2  = (const float*)d_in[4];
    const float* W3  = (const float*)d_in[5];
    const float* b3  = (const float*)d_in[6];
    const int*   T   = (const int*)  d_in[7];
    float* out = (float*)d_out;

    const int nTraj = in_sizes[0] / DIM;
    const int trajElems = nTraj * TRAJ_LEN * DIM;
    const int writeN = (out_size > trajElems) ? 1 : 0;

    if (writeN) {
        cudaMemsetAsync((char*)d_out + (size_t)trajElems * sizeof(float), 0,
                        (size_t)(out_size - trajElems) * sizeof(float), 0);
    }

    const int nPair = (nTraj + 1) / 2;
    ode_kernel<<<nPair, 32>>>(x0s, W1, b1, W2, b2, W3, b3, T, out, nTraj, writeN);
}

// round 17
// speedup vs baseline: 1.1621x; 1.1621x over previous
#include <cuda_runtime.h>
#include <math.h>

// ---------------------------------------------------------------------------
// NeuralODE Tsit5, TWO trajectories per warp (shared weight registers,
// interleaved independent chains), f32x2-packed, FSAL, LDS ping-pong
// broadcasts WITHOUT warpsync (convergent-warp lockstep + depth-2 buffers).
// Lane L owns components (2L, 2L+1) of both trajectories.
// ---------------------------------------------------------------------------

#define DIM      64
#define HID      32
#define TRAJ_LEN 11
#define MAXI     64

typedef unsigned long long u64;

__device__ __forceinline__ u64 pk2(float lo, float hi) {
    u64 r; asm("mov.b64 %0,{%1,%2};" : "=l"(r) : "f"(lo), "f"(hi)); return r;
}
__device__ __forceinline__ u64 pkb(float x) { return pk2(x, x); }
__device__ __forceinline__ void upk(u64 v, float& a, float& b) {
    asm("mov.b64 {%0,%1},%2;" : "=f"(a), "=f"(b) : "l"(v));
}
__device__ __forceinline__ u64 fma2(u64 a, u64 b, u64 c) {
    u64 d; asm("fma.rn.f32x2 %0,%1,%2,%3;" : "=l"(d) : "l"(a), "l"(b), "l"(c)); return d;
}
__device__ __forceinline__ u64 add2(u64 a, u64 b) {
    u64 d; asm("add.rn.f32x2 %0,%1,%2;" : "=l"(d) : "l"(a), "l"(b)); return d;
}
__device__ __forceinline__ u64 mul2(u64 a, u64 b) {
    u64 d; asm("mul.rn.f32x2 %0,%1,%2;" : "=l"(d) : "l"(a), "l"(b)); return d;
}
__device__ __forceinline__ float hsum2(u64 v) { float a, b; upk(v, a, b); return a + b; }

// Tsit5 tableau (f32) — C_ namespace, no identifier collisions
#define C_A21 ((float)0.161)
#define C_A31 ((float)-0.008480655492356989)
#define C_A32 ((float)0.335480655492357)
#define C_A41 ((float)2.8971530571054935)
#define C_A42 ((float)-6.359448489975075)
#define C_A43 ((float)4.3622954328695815)
#define C_A51 ((float)5.325864828439257)
#define C_A52 ((float)-11.748883564062828)
#define C_A53 ((float)7.4955393428898365)
#define C_A54 ((float)-0.09249506636175525)
#define C_A61 ((float)5.86145544294642)
#define C_A62 ((float)-12.92096931784711)
#define C_A63 ((float)8.159367898576159)
#define C_A64 ((float)-0.071584973281401)
#define C_A65 ((float)-0.028269050394068383)
#define C_B1  ((float)0.09646076681806523)
#define C_B2  ((float)0.01)
#define C_B3  ((float)0.4798896504144996)
#define C_B4  ((float)1.379008574103742)
#define C_B5  ((float)-3.290069515436081)
#define C_B6  ((float)2.324710524099774)
#define C_E1  ((float)-0.00178001105222577714)
#define C_E2  ((float)-0.0008164344596567469)
#define C_E3  ((float)0.007880878010261995)
#define C_E4  ((float)-0.1447110071732629)
#define C_E5  ((float)0.5823571654525552)
#define C_E6  ((float)-0.45808210592918697)
#define C_E7  ((float)0.015151515151515152)

#define RTOL 1e-3f
#define ATOL 1e-6f

__device__ __forceinline__ float softplus_f(float x) {
    return fmaxf(x, 0.0f) + __logf(1.0f + __expf(-fabsf(x)));
}

// Compiler-level ordering only: the warp is convergent (all control flow
// around FEVAL2 is warp-uniform), lanes run lockstep, and ping-pong depth-2
// guarantees a buffer is rewritten only two broadcasts after its last read.
#define CBAR() asm volatile("" ::: "memory")

#define BC64x2(ZA, ZB) do { bsel ^= 1;                                          \
    float* _ba = bsel ? bA0 : bA1; float* _bb = bsel ? bB0 : bB1;               \
    ((u64*)_ba)[lane] = (ZA); ((u64*)_bb)[lane] = (ZB);                         \
    CBAR(); curA = _ba; curB = _bb; } while (0)
#define BC32x2(HA, HB) do { bsel ^= 1;                                          \
    float* _ba = bsel ? bA0 : bA1; float* _bb = bsel ? bB0 : bB1;               \
    _ba[lane] = (HA); _bb[lane] = (HB);                                         \
    CBAR(); curA = _ba; curB = _bb; } while (0)

// Dual MLP eval: two independent chains interleaved for ILP.
#define FEVAL2(ZA, ZB, KA, KB) do {                                             \
    BC64x2(ZA, ZB);                                                             \
    { const ulonglong2* _zA = (const ulonglong2*)curA;                          \
      const ulonglong2* _zB = (const ulonglong2*)curB;                          \
      u64 _aA0=0,_aA1=0,_aA2=0,_aA3=0, _aB0=0,_aB1=0,_aB2=0,_aB3=0;             \
      _Pragma("unroll")                                                         \
      for (int _j = 0; _j < 8; _j++) {                                          \
          ulonglong2 _pA = _zA[2*_j], _rA = _zA[2*_j+1];                        \
          ulonglong2 _pB = _zB[2*_j], _rB = _zB[2*_j+1];                        \
          _aA0 = fma2(w1p[4*_j+0], _pA.x, _aA0);                                \
          _aB0 = fma2(w1p[4*_j+0], _pB.x, _aB0);                                \
          _aA1 = fma2(w1p[4*_j+1], _pA.y, _aA1);                                \
          _aB1 = fma2(w1p[4*_j+1], _pB.y, _aB1);                                \
          _aA2 = fma2(w1p[4*_j+2], _rA.x, _aA2);                                \
          _aB2 = fma2(w1p[4*_j+2], _rB.x, _aB2);                                \
          _aA3 = fma2(w1p[4*_j+3], _rA.y, _aA3);                                \
          _aB3 = fma2(w1p[4*_j+3], _rB.y, _aB3);                                \
      }                                                                         \
      float _h1A = softplus_f(hsum2(add2(add2(_aA0,_aA1), add2(_aA2,_aA3))) + bb1); \
      float _h1B = softplus_f(hsum2(add2(add2(_aB0,_aB1), add2(_aB2,_aB3))) + bb1); \
      BC32x2(_h1A, _h1B);                                                       \
      const ulonglong2* _hA = (const ulonglong2*)curA;                          \
      const ulonglong2* _hB = (const ulonglong2*)curB;                          \
      u64 _sA0=0,_sA1=0, _sB0=0,_sB1=0;                                         \
      _Pragma("unroll")                                                         \
      for (int _j = 0; _j < 4; _j++) {                                          \
          ulonglong2 _qA = _hA[2*_j], _gA = _hA[2*_j+1];                        \
          ulonglong2 _qB = _hB[2*_j], _gB = _hB[2*_j+1];                        \
          _sA0 = fma2(w2p[4*_j+0], _qA.x, _sA0);                                \
          _sB0 = fma2(w2p[4*_j+0], _qB.x, _sB0);                                \
          _sA1 = fma2(w2p[4*_j+1], _qA.y, _sA1);                                \
          _sB1 = fma2(w2p[4*_j+1], _qB.y, _sB1);                                \
          _sA0 = fma2(w2p[4*_j+2], _gA.x, _sA0);                                \
          _sB0 = fma2(w2p[4*_j+2], _gB.x, _sB0);                                \
          _sA1 = fma2(w2p[4*_j+3], _gA.y, _sA1);                                \
          _sB1 = fma2(w2p[4*_j+3], _gB.y, _sB1);                                \
      }                                                                         \
      float _h2A = softplus_f(hsum2(add2(_sA0,_sA1)) + bb2);                    \
      float _h2B = softplus_f(hsum2(add2(_sB0,_sB1)) + bb2);                    \
      BC32x2(_h2A, _h2B);                                                       \
      const ulonglong2* _gpA = (const ulonglong2*)curA;                         \
      const ulonglong2* _gpB = (const ulonglong2*)curB;                         \
      u64 _cA0=0,_cA1=0,_dA0=0,_dA1=0, _cB0=0,_cB1=0,_dB0=0,_dB1=0;             \
      _Pragma("unroll")                                                         \
      for (int _j = 0; _j < 4; _j++) {                                          \
          ulonglong2 _qA = _gpA[2*_j], _gA = _gpA[2*_j+1];                      \
          ulonglong2 _qB = _gpB[2*_j], _gB = _gpB[2*_j+1];                      \
          _cA0 = fma2(w3p0[4*_j+0], _qA.x, _cA0);                               \
          _cB0 = fma2(w3p0[4*_j+0], _qB.x, _cB0);                               \
          _cA1 = fma2(w3p0[4*_j+1], _qA.y, _cA1);                               \
          _cB1 = fma2(w3p0[4*_j+1], _qB.y, _cB1);                               \
          _cA0 = fma2(w3p0[4*_j+2], _gA.x, _cA0);                               \
          _cB0 = fma2(w3p0[4*_j+2], _gB.x, _cB0);                               \
          _cA1 = fma2(w3p0[4*_j+3], _gA.y, _cA1);                               \
          _cB1 = fma2(w3p0[4*_j+3], _gB.y, _cB1);                               \
          _dA0 = fma2(w3p1[4*_j+0], _qA.x, _dA0);                               \
          _dB0 = fma2(w3p1[4*_j+0], _qB.x, _dB0);                               \
          _dA1 = fma2(w3p1[4*_j+1], _qA.y, _dA1);                               \
          _dB1 = fma2(w3p1[4*_j+1], _qB.y, _dB1);                               \
          _dA0 = fma2(w3p1[4*_j+2], _gA.x, _dA0);                               \
          _dB0 = fma2(w3p1[4*_j+2], _gB.x, _dB0);                               \
          _dA1 = fma2(w3p1[4*_j+3], _gA.y, _dA1);                               \
          _dB1 = fma2(w3p1[4*_j+3], _gB.y, _dB1);                               \
      }                                                                         \
      (KA) = pk2(hsum2(add2(_cA0,_cA1)) + b3x, hsum2(add2(_dA0,_dA1)) + b3y);   \
      (KB) = pk2(hsum2(add2(_cB0,_cB1)) + b3x, hsum2(add2(_dB0,_dB1)) + b3y);   \
    } } while (0)

__global__ void __launch_bounds__(32, 8)
ode_kernel(const float* __restrict__ x0s,
           const float* __restrict__ gW1, const float* __restrict__ gb1,
           const float* __restrict__ gW2, const float* __restrict__ gb2,
           const float* __restrict__ gW3, const float* __restrict__ gb3,
           const int*   __restrict__ Tp,
           float* __restrict__ out, int nTraj, int writeN)
{
    __shared__ __align__(16) float bA0[DIM], bA1[DIM], bB0[DIM], bB1[DIM];

    const int lane  = threadIdx.x & 31;
    const int trajA = blockIdx.x * 2;
    const int trajB = trajA + 1;
    if (trajA >= nTraj) return;
    const bool hasB = (trajB < nTraj);

    int bsel = 0;
    const float* curA = bA0;
    const float* curB = bB0;

    // Shared weight registers: lane owns W1 row L, W2 row L, W3 rows 2L, 2L+1.
    u64 w1p[32], w2p[16], w3p0[16], w3p1[16];
    {
        const u64* r1 = (const u64*)(gW1 + lane * DIM);
        #pragma unroll
        for (int j = 0; j < 32; j++) w1p[j] = __ldg(r1 + j);
        const u64* r2 = (const u64*)(gW2 + lane * HID);
        #pragma unroll
        for (int j = 0; j < 16; j++) w2p[j] = __ldg(r2 + j);
        const u64* r3a = (const u64*)(gW3 + (2*lane)   * HID);
        const u64* r3b = (const u64*)(gW3 + (2*lane+1) * HID);
        #pragma unroll
        for (int j = 0; j < 16; j++) { w3p0[j] = __ldg(r3a + j); w3p1[j] = __ldg(r3b + j); }
    }
    const float bb1 = __ldg(gb1 + lane);
    const float bb2 = __ldg(gb2 + lane);
    const float b3x = __ldg(gb3 + 2*lane);
    const float b3y = __ldg(gb3 + 2*lane + 1);

    u64 yA = ((const u64*)(x0s + (size_t)trajA * DIM))[lane];
    u64 yB = hasB ? ((const u64*)(x0s + (size_t)trajB * DIM))[lane] : yA;

    float* orowA = out + (size_t)trajA * (TRAJ_LEN * DIM);
    float* orowB = out + (size_t)trajB * (TRAJ_LEN * DIM);
    ((u64*)orowA)[lane] = yA;
    if (hasB) ((u64*)orowB)[lane] = yB;

    const float Tf   = (float)__ldg(Tp);
    const float step = Tf / 10.0f;
    float tA = 0.0f, tB = 0.0f;
    float dtA = 1e-3f, dtB = 1e-3f;
    int   nA = 0, nB = 0;

    // FSAL seed
    u64 k1A, k1B;
    FEVAL2(yA, yB, k1A, k1B);

    for (int iv = 1; iv < TRAJ_LEN; iv++) {
        const float t_target = step * (float)iv;

        for (int it = 0; it < MAXI; it++) {
            float remA = t_target - tA;
            float remB = t_target - tB;
            bool doneA = (remA <= 1e-12f);
            bool doneB = (remB <= 1e-12f);
            if (doneA && doneB) break;          // ref freezes state when done: exact
            nA += doneA ? 0 : 1;
            nB += doneB ? 0 : 1;

            float hA = fminf(dtA, fmaxf(remA, 0.0f));
            float hB = fminf(dtB, fmaxf(remB, 0.0f));

            u64 k2A,k3A,k4A,k5A,k6A,k7A, k2B,k3B,k4B,k5B,k6B,k7B, zA, zB;

            zA = fma2(pkb(hA*C_A21), k1A, yA);
            zB = fma2(pkb(hB*C_A21), k1B, yB);
            FEVAL2(zA, zB, k2A, k2B);

            zA = fma2(pkb(hA*C_A31), k1A, fma2(pkb(hA*C_A32), k2A, yA));
            zB = fma2(pkb(hB*C_A31), k1B, fma2(pkb(hB*C_A32), k2B, yB));
            FEVAL2(zA, zB, k3A, k3B);

            zA = fma2(pkb(hA*C_A41), k1A, fma2(pkb(hA*C_A42), k2A, fma2(pkb(hA*C_A43), k3A, yA)));
            zB = fma2(pkb(hB*C_A41), k1B, fma2(pkb(hB*C_A42), k2B, fma2(pkb(hB*C_A43), k3B, yB)));
            FEVAL2(zA, zB, k4A, k4B);

            zA = fma2(pkb(hA*C_A51), k1A, fma2(pkb(hA*C_A52), k2A, fma2(pkb(hA*C_A53), k3A,
                 fma2(pkb(hA*C_A54), k4A, yA))));
            zB = fma2(pkb(hB*C_A51), k1B, fma2(pkb(hB*C_A52), k2B, fma2(pkb(hB*C_A53), k3B,
                 fma2(pkb(hB*C_A54), k4B, yB))));
            FEVAL2(zA, zB, k5A, k5B);

            zA = fma2(pkb(hA*C_A61), k1A, fma2(pkb(hA*C_A62), k2A, fma2(pkb(hA*C_A63), k3A,
                 fma2(pkb(hA*C_A64), k4A, fma2(pkb(hA*C_A65), k5A, yA)))));
            zB = fma2(pkb(hB*C_A61), k1B, fma2(pkb(hB*C_A62), k2B, fma2(pkb(hB*C_A63), k3B,
                 fma2(pkb(hB*C_A64), k4B, fma2(pkb(hB*C_A65), k5B, yB)))));
            FEVAL2(zA, zB, k6A, k6B);

            u64 y5A = fma2(pkb(hA*C_B1), k1A, fma2(pkb(hA*C_B2), k2A, fma2(pkb(hA*C_B3), k3A,
                      fma2(pkb(hA*C_B4), k4A, fma2(pkb(hA*C_B5), k5A, fma2(pkb(hA*C_B6), k6A, yA))))));
            u64 y5B = fma2(pkb(hB*C_B1), k1B, fma2(pkb(hB*C_B2), k2B, fma2(pkb(hB*C_B3), k3B,
                      fma2(pkb(hB*C_B4), k4B, fma2(pkb(hB*C_B5), k5B, fma2(pkb(hB*C_B6), k6B, yB))))));

            FEVAL2(y5A, y5B, k7A, k7B);

            u64 errA = fma2(pkb(hA*C_E1), k1A, fma2(pkb(hA*C_E2), k2A, fma2(pkb(hA*C_E3), k3A,
                       fma2(pkb(hA*C_E4), k4A, fma2(pkb(hA*C_E5), k5A, fma2(pkb(hA*C_E6), k6A,
                       mul2(pkb(hA*C_E7), k7A)))))));
            u64 errB = fma2(pkb(hB*C_E1), k1B, fma2(pkb(hB*C_E2), k2B, fma2(pkb(hB*C_E3), k3B,
                       fma2(pkb(hB*C_E4), k4B, fma2(pkb(hB*C_E5), k5B, fma2(pkb(hB*C_E6), k6B,
                       mul2(pkb(hB*C_E7), k7B)))))));

            float ylo, yhi, y5lo, y5hi, elo, ehi;
            upk(yA, ylo, yhi); upk(y5A, y5lo, y5hi); upk(errA, elo, ehi);
            float sclo = fmaf(RTOL, fmaxf(fabsf(ylo), fabsf(y5lo)), ATOL);
            float schi = fmaf(RTOL, fmaxf(fabsf(yhi), fabsf(y5hi)), ATOL);
            float rlo = __fdividef(elo, sclo);
            float rhi = __fdividef(ehi, schi);
            float ssA = fmaf(rlo, rlo, rhi * rhi);

            upk(yB, ylo, yhi); upk(y5B, y5lo, y5hi); upk(errB, elo, ehi);
            sclo = fmaf(RTOL, fmaxf(fabsf(ylo), fabsf(y5lo)), ATOL);
            schi = fmaf(RTOL, fmaxf(fabsf(yhi), fabsf(y5hi)), ATOL);
            rlo = __fdividef(elo, sclo);
            rhi = __fdividef(ehi, schi);
            float ssB = fmaf(rlo, rlo, rhi * rhi);

            #pragma unroll
            for (int o = 16; o; o >>= 1) {
                ssA += __shfl_xor_sync(0xffffffffu, ssA, o);
                ssB += __shfl_xor_sync(0xffffffffu, ssB, o);
            }

            bool acceptA = (ssA <= 64.0f);      // == (max(sqrt(ss/64),1e-10) <= 1)
            bool acceptB = (ssB <= 64.0f);
            float qA = fmaxf(ssA * 0.015625f, 1e-20f);
            float qB = fmaxf(ssB * 0.015625f, 1e-20f);
            float facA = fminf(fmaxf(0.9f * __powf(qA, -0.1f), 0.1f), 5.0f);
            float facB = fminf(fmaxf(0.9f * __powf(qB, -0.1f), 0.1f), 5.0f);

            if (!doneA) {
                if (acceptA) { tA += hA; yA = y5A; k1A = k7A; }
                dtA = fmaxf(hA * facA, 1e-8f);
            }
            if (!doneB) {
                if (acceptB) { tB += hB; yB = y5B; k1B = k7B; }
                dtB = fmaxf(hB * facB, 1e-8f);
            }
        }

        ((u64*)(orowA + iv * DIM))[lane] = yA;
        if (hasB) ((u64*)(orowB + iv * DIM))[lane] = yB;
    }

    if (writeN && lane == 0)
        atomicAdd(out + (size_t)nTraj * TRAJ_LEN * DIM, (float)(nA + (hasB ? nB : 0)));
}

extern "C" void kernel_launch(void* const* d_in, const int* in_sizes, int n_in,
                              void* d_out, int out_size)
{
    const float* x0s = (const float*)d_in[0];
    const float* W1  = (const float*)d_in[1];
    const float* b1  = (const float*)d_in[2];
    const float* W2  = (const float*)d_in[3];
    const float* b2  = (const float*)d_in[4];
    const float* W3  = (const float*)d_in[5];
    const float* b3  = (const float*)d_in[6];
    const int*   T   = (const int*)  d_in[7];
    float* out = (float*)d_out;

    const int nTraj = in_sizes[0] / DIM;
    const int trajElems = nTraj * TRAJ_LEN * DIM;
    const int writeN = (out_size > trajElems) ? 1 : 0;

    if (writeN) {
        cudaMemsetAsync((char*)d_out + (size_t)trajElems * sizeof(float), 0,
                        (size_t)(out_size - trajElems) * sizeof(float), 0);
    }

    const int nPair = (nTraj + 1) / 2;
    ode_kernel<<<nPair, 32>>>(x0s, W1, b1, W2, b2, W3, b3, T, out, nTraj, writeN);
}